// round 1
// baseline (speedup 1.0000x reference)
#include <cuda_runtime.h>
#include <cstdint>

#define BB 256
#define MM 80
#define TT 1000
#define HH 128
#define GG (3*HH)   // 384

#define TILE_T 128
#define K1_THREADS 384
#define WPAD 385

// scratch: gx[b][t][g]  (393 MB)
__device__ float g_gx[(size_t)BB * TT * GG];

// ---------------- packed f32x2 helpers ----------------
__device__ __forceinline__ unsigned long long pack2(float lo, float hi) {
    unsigned long long r;
    asm("mov.b64 %0, {%1,%2};" : "=l"(r) : "f"(lo), "f"(hi));
    return r;
}
__device__ __forceinline__ void unpack2(unsigned long long v, float& lo, float& hi) {
    asm("mov.b64 {%0,%1}, %2;" : "=f"(lo), "=f"(hi) : "l"(v));
}
__device__ __forceinline__ unsigned long long ffma2(unsigned long long a,
                                                    unsigned long long b,
                                                    unsigned long long c) {
    unsigned long long d;
    asm("fma.rn.f32x2 %0, %1, %2, %3;" : "=l"(d) : "l"(a), "l"(b), "l"(c));
    return d;
}

__device__ __forceinline__ float fast_sigmoid(float x) {
    float e = __expf(-x);                 // large x -> 0 -> 1 ; very neg x -> inf -> 0
    return __fdividef(1.0f, 1.0f + e);
}
__device__ __forceinline__ float fast_tanh(float x) {
    float ax = fabsf(x);
    float e = __expf(-2.0f * ax);         // in (0,1], no overflow
    float t = __fdividef(1.0f - e, 1.0f + e);
    return copysignf(t, x);
}

// ================= Kernel 1: gx = x^T @ W_ih^T + b_ih =================
// grid: (T/TILE_T, B), 384 threads. Each thread owns one g, 16-t chunks.
__global__ __launch_bounds__(K1_THREADS)
void gx_kernel(const float* __restrict__ x,
               const float* __restrict__ W_ih,
               const float* __restrict__ b_ih)
{
    extern __shared__ float sm[];
    float* Wsh = sm;                         // [MM][WPAD] transposed (m-major)
    float* xsh = sm + MM * WPAD;             // [MM][TILE_T]
    const int tid = threadIdx.x;
    const int b   = blockIdx.y;
    const int t0  = blockIdx.x * TILE_T;

    // W transpose into smem: coalesced global reads, conflict-free STS (pad 385)
    for (int idx = tid; idx < GG * MM; idx += K1_THREADS) {
        int g = idx / MM, m = idx % MM;      // idx == g*MM+m, contiguous reads
        Wsh[m * WPAD + g] = W_ih[idx];
    }
    // x tile (zero-pad past T)
    for (int idx = tid; idx < MM * TILE_T; idx += K1_THREADS) {
        int m = idx / TILE_T, tt = idx % TILE_T;
        int t = t0 + tt;
        xsh[m * TILE_T + tt] = (t < TT) ? x[((size_t)b * MM + m) * TT + t] : 0.0f;
    }
    __syncthreads();

    const int g = tid;
    const float bih = b_ih[g];
    const unsigned long long* xsh2 = (const unsigned long long*)xsh;

    for (int c = 0; c < TILE_T / 16; c++) {
        unsigned long long acc[8];
        #pragma unroll
        for (int i = 0; i < 8; i++) acc[i] = 0ULL;

        #pragma unroll 8
        for (int m = 0; m < MM; m++) {
            float w = Wsh[m * WPAD + g];
            unsigned long long w2 = pack2(w, w);
            const ulonglong2* xp = (const ulonglong2*)&xsh2[m * (TILE_T / 2) + c * 8];
            #pragma unroll
            for (int i = 0; i < 4; i++) {
                ulonglong2 xv = xp[i];
                acc[2 * i]     = ffma2(w2, xv.x, acc[2 * i]);
                acc[2 * i + 1] = ffma2(w2, xv.y, acc[2 * i + 1]);
            }
        }
        const int tbase = t0 + c * 16;
        #pragma unroll
        for (int i = 0; i < 8; i++) {
            float lo, hi;
            unpack2(acc[i], lo, hi);
            int t = tbase + 2 * i;
            if (t < TT)     g_gx[((size_t)b * TT + t) * GG + g]     = lo + bih;
            if (t + 1 < TT) g_gx[((size_t)b * TT + t + 1) * GG + g] = hi + bih;
        }
    }
}

// ================= Kernel 2: sequential GRU recurrence =================
// 128 blocks, 2 batches each, 384 threads. W_hh row lives packed in registers.
__global__ __launch_bounds__(K1_THREADS, 1)
void gru_kernel(const float* __restrict__ W_hh,
                const float* __restrict__ b_hh,
                float* __restrict__ out)
{
    __shared__ __align__(16) float hs0[HH];
    __shared__ __align__(16) float hs1[HH];
    __shared__ float gh0[GG], gh1[GG];
    __shared__ float gxs0[GG], gxs1[GG];

    const int tid = threadIdx.x;
    const int g = tid;                       // 0..383
    const int b0 = blockIdx.x * 2;
    const int b1 = b0 + 1;

    // pack W_hh[g][:] into 64 f32x2 registers (reused for all 1000 steps)
    unsigned long long wreg[HH / 2];
    {
        const float4* wr = (const float4*)(W_hh + (size_t)g * HH);
        #pragma unroll
        for (int j = 0; j < HH / 4; j++) {
            float4 v = wr[j];
            wreg[2 * j]     = pack2(v.x, v.y);
            wreg[2 * j + 1] = pack2(v.z, v.w);
        }
    }
    const float bh = b_hh[g];

    if (tid < HH) { hs0[tid] = 0.0f; hs1[tid] = 0.0f; }
    __syncthreads();

    const float* gx0p = g_gx + (size_t)b0 * TT * GG + g;
    const float* gx1p = g_gx + (size_t)b1 * TT * GG + g;

    for (int t = 0; t < TT; t++) {
        // prefetch this step's input-side gates (hidden under the dot product)
        float gx0 = gx0p[(size_t)t * GG];
        float gx1 = gx1p[(size_t)t * GG];

        unsigned long long a0 = 0ULL, a1 = 0ULL, a2 = 0ULL, a3 = 0ULL;
        const ulonglong2* h0v = (const ulonglong2*)hs0;
        const ulonglong2* h1v = (const ulonglong2*)hs1;
        #pragma unroll
        for (int j = 0; j < HH / 4; j++) {
            ulonglong2 v0 = h0v[j];
            ulonglong2 v1 = h1v[j];
            a0 = ffma2(wreg[2 * j],     v0.x, a0);
            a1 = ffma2(wreg[2 * j + 1], v0.y, a1);
            a2 = ffma2(wreg[2 * j],     v1.x, a2);
            a3 = ffma2(wreg[2 * j + 1], v1.y, a3);
        }
        float l, h;
        float s0, s1;
        unpack2(a0, l, h); s0 = l + h;
        unpack2(a1, l, h); s0 += l + h;
        unpack2(a2, l, h); s1 = l + h;
        unpack2(a3, l, h); s1 += l + h;

        gh0[g] = s0 + bh;
        gh1[g] = s1 + bh;
        gxs0[g] = gx0;
        gxs1[g] = gx1;
        __syncthreads();

        if (tid < 2 * HH) {
            const int bb = tid >> 7;         // 0 or 1
            const int j  = tid & (HH - 1);
            const float* ghp = bb ? gh1 : gh0;
            const float* gxp = bb ? gxs1 : gxs0;
            float* hp = bb ? hs1 : hs0;
            float r = fast_sigmoid(gxp[j]          + ghp[j]);
            float z = fast_sigmoid(gxp[j + HH]     + ghp[j + HH]);
            float n = fast_tanh   (gxp[j + 2 * HH] + r * ghp[j + 2 * HH]);
            hp[j] = (1.0f - z) * n + z * hp[j];
        }
        __syncthreads();
    }

    if (tid < 2 * HH) {
        const int bb = tid >> 7;
        const int j  = tid & (HH - 1);
        out[(size_t)(b0 + bb) * HH + j] = (bb ? hs1 : hs0)[j];
    }
}

// ================= launch =================
extern "C" void kernel_launch(void* const* d_in, const int* in_sizes, int n_in,
                              void* d_out, int out_size)
{
    const float* x    = (const float*)d_in[0];
    const float* W_ih = (const float*)d_in[1];
    const float* W_hh = (const float*)d_in[2];
    const float* b_ih = (const float*)d_in[3];
    const float* b_hh = (const float*)d_in[4];
    float* out = (float*)d_out;

    size_t smem1 = (size_t)(MM * WPAD + MM * TILE_T) * sizeof(float); // ~160 KB
    cudaFuncSetAttribute(gx_kernel, cudaFuncAttributeMaxDynamicSharedMemorySize,
                         (int)smem1);

    dim3 grid1((TT + TILE_T - 1) / TILE_T, BB);
    gx_kernel<<<grid1, K1_THREADS, smem1>>>(x, W_ih, b_ih);
    gru_kernel<<<BB / 2, K1_THREADS>>>(W_hh, b_hh, out);
}